// round 9
// baseline (speedup 1.0000x reference)
#include <cuda_runtime.h>
#include <cstdint>
#include <cstddef>

#define T_SEQ   12
#define BATCH   2048
#define IN_DIM  512
#define HIDDEN  1024

// ---------------- scratch (no runtime allocation allowed) ----------------
__device__ float d_H [BATCH * HIDDEN];                       // current hidden state
__device__ float d_RH[BATCH * HIDDEN];                       // r * h
__device__ float d_U [BATCH * HIDDEN];                       // update gate
__device__ float d_Gx[(size_t)BATCH * T_SEQ * 2 * HIDDEN];   // x@Wg_x + bg
__device__ float d_Cx[(size_t)BATCH * T_SEQ * HIDDEN];       // x@Wc_x + bc

// ---------------- mma / cp.async helpers ----------------
__device__ __forceinline__ void mma_tf32(float c[4], const uint32_t a[4], const uint32_t b[2]) {
    asm volatile(
        "mma.sync.aligned.m16n8k8.row.col.f32.tf32.tf32.f32 "
        "{%0,%1,%2,%3}, {%4,%5,%6,%7}, {%8,%9}, {%0,%1,%2,%3};\n"
        : "+f"(c[0]), "+f"(c[1]), "+f"(c[2]), "+f"(c[3])
        : "r"(a[0]), "r"(a[1]), "r"(a[2]), "r"(a[3]), "r"(b[0]), "r"(b[1]));
}

__device__ __forceinline__ void cp_async16(uint32_t dst, const void* src) {
    asm volatile("cp.async.cg.shared.global [%0], [%1], 16;\n" :: "r"(dst), "l"(src));
}

// ---------------- shared GEMM core: 128x128 block tile, BK=32, 256 threads ----------------
// 8 warps as 2 (M) x 4 (N); warp tile 64x32; 4x4 m16n8k8 mma tiles.
// 3-stage cp.async ring, ONE barrier per K-slab. Raw fp32 bits fed to tf32 MMA.
#define BM 128
#define BN 128
#define BK 32
#define NSTAGE 3
#define SA_STRIDE 36   // BK + 4
#define SB_STRIDE 136  // BN + 8
#define SA_ELEMS  (BM * SA_STRIDE)
#define SB_ELEMS  (BK * SB_STRIDE)
#define STAGE_ELEMS (SA_ELEMS + SB_ELEMS)
#define SMEM_BYTES (NSTAGE * STAGE_ELEMS * 4)   // 107520

__device__ __forceinline__ void load_stage(
    uint32_t stage_addr,
    const float* __restrict__ A, int lda,
    const float* __restrict__ B, int ldb,
    int block_row, int block_col, int k0, int tid)
{
    const uint32_t sA_addr = stage_addr;
    const uint32_t sB_addr = stage_addr + SA_ELEMS * 4;
#pragma unroll
    for (int i = 0; i < 4; i++) {
        int idx = tid + i * 256;
        int r = idx >> 3, c = (idx & 7) << 2;
        cp_async16(sA_addr + (uint32_t)(r * SA_STRIDE + c) * 4,
                   A + (size_t)(block_row + r) * lda + k0 + c);
    }
#pragma unroll
    for (int i = 0; i < 4; i++) {
        int idx = tid + i * 256;
        int r = idx >> 5, c = (idx & 31) << 2;
        cp_async16(sB_addr + (uint32_t)(r * SB_STRIDE + c) * 4,
                   B + (size_t)(k0 + r) * ldb + block_col + c);
    }
    asm volatile("cp.async.commit_group;\n" ::: "memory");
}

__device__ __forceinline__ void gemm_core(
    const float* __restrict__ A, int lda,
    const float* __restrict__ B, int ldb,
    int K, int block_row, int block_col,
    float acc[4][4][4])
{
    extern __shared__ uint32_t smem[];

    const int tid  = threadIdx.x;
    const int lane = tid & 31;
    const int warp = tid >> 5;
    const int wm   = warp & 1;
    const int wn   = warp >> 1;

    const uint32_t smem_base = (uint32_t)__cvta_generic_to_shared(smem);

#pragma unroll
    for (int mi = 0; mi < 4; mi++)
#pragma unroll
        for (int ni = 0; ni < 4; ni++)
#pragma unroll
            for (int r = 0; r < 4; r++) acc[mi][ni][r] = 0.0f;

    const int nsteps = K / BK;

    // prologue: stages 0 and 1 in flight
    load_stage(smem_base, A, lda, B, ldb, block_row, block_col, 0, tid);
    load_stage(smem_base + STAGE_ELEMS * 4, A, lda, B, ldb, block_row, block_col, BK, tid);

    int mbuf = 0;      // stage consumed this iteration  (s % 3)
    int lbuf = 2;      // stage loaded this iteration    ((s+2) % 3)

    for (int s = 0; s < nsteps; s++) {
        if (s == nsteps - 1)
            asm volatile("cp.async.wait_group 0;\n" ::: "memory");
        else
            asm volatile("cp.async.wait_group 1;\n" ::: "memory");
        __syncthreads();   // all warps done with stage (s-1); stage s visible

        if (s + 2 < nsteps) {
            load_stage(smem_base + (uint32_t)lbuf * STAGE_ELEMS * 4,
                       A, lda, B, ldb, block_row, block_col, (s + 2) * BK, tid);
        }
        lbuf = (lbuf == NSTAGE - 1) ? 0 : lbuf + 1;

        const uint32_t* cA = smem + (size_t)mbuf * STAGE_ELEMS;
        const uint32_t* cB = cA + SA_ELEMS;
        mbuf = (mbuf == NSTAGE - 1) ? 0 : mbuf + 1;

#pragma unroll
        for (int ks = 0; ks < 4; ks++) {
            const int kk = ks * 8;
            uint32_t af[4][4], bf[4][2];
#pragma unroll
            for (int mi = 0; mi < 4; mi++) {
                int rb = wm * 64 + mi * 16 + (lane >> 2);
                const uint32_t* p = cA + rb * SA_STRIDE + kk + (lane & 3);
                af[mi][0] = p[0];
                af[mi][1] = p[8 * SA_STRIDE];
                af[mi][2] = p[4];
                af[mi][3] = p[8 * SA_STRIDE + 4];
            }
#pragma unroll
            for (int ni = 0; ni < 4; ni++) {
                int cb = wn * 32 + ni * 8 + (lane >> 2);
                const uint32_t* p = cB + (kk + (lane & 3)) * SB_STRIDE + cb;
                bf[ni][0] = p[0];
                bf[ni][1] = p[4 * SB_STRIDE];
            }
#pragma unroll
            for (int mi = 0; mi < 4; mi++)
#pragma unroll
                for (int ni = 0; ni < 4; ni++)
                    mma_tf32(acc[mi][ni], af[mi], bf[ni]);
        }
        // no trailing barrier: next iteration's load targets a buffer that is
        // provably idle once all warps pass the barrier above (3-stage ring)
    }
}

#define EPI_COORDS()                                          \
    const int lane = threadIdx.x & 31;                        \
    const int warp = threadIdx.x >> 5;                        \
    const int wm = warp & 1, wn = warp >> 1;                  \
    const int block_row = blockIdx.y * BM;

__device__ __forceinline__ float sigmoidf_(float x) { return 1.0f / (1.0f + expf(-x)); }

// ---------------- kernel: h <- coded_cords ----------------
__global__ __launch_bounds__(256) void init_h_kernel(const float* __restrict__ src) {
    size_t i = (size_t)blockIdx.x * 256 + threadIdx.x;
    ((float4*)d_H)[i] = ((const float4*)src)[i];
}

// ---------------- fused gate kernel ----------------
// blocks with blockIdx.x <  nx : gate step t  = sigmoid(Gx_t + H @ Wg_h) -> RH, U
// blocks with blockIdx.x >= nx : precompute Gx chunk for t+1 = x_{t+1} @ Wg_x + bg
__global__ __launch_bounds__(256) void gate_fused_kernel(
    const float* __restrict__ x, const float* __restrict__ Wg,
    const float* __restrict__ bg, int t, int nx)
{
    float acc[4][4][4];
    EPI_COORDS();

    if ((int)blockIdx.x < nx) {
        const int block_col = blockIdx.x * BN;
        gemm_core(d_H, HIDDEN, Wg + (size_t)IN_DIM * 2 * HIDDEN, 2 * HIDDEN, HIDDEN,
                  block_row, block_col, acc);
        const bool is_reset = (block_col < HIDDEN);   // uniform per block
#pragma unroll
        for (int mi = 0; mi < 4; mi++)
#pragma unroll
            for (int ni = 0; ni < 4; ni++) {
                int row0 = block_row + wm * 64 + mi * 16 + (lane >> 2);
                int col  = block_col + wn * 32 + ni * 8 + ((lane & 3) << 1);
#pragma unroll
                for (int p = 0; p < 2; p++) {
                    int row = row0 + p * 8;
                    float2 gx = *(const float2*)&d_Gx[(size_t)(row * T_SEQ + t) * (2 * HIDDEN) + col];
                    float g0 = sigmoidf_(acc[mi][ni][2 * p + 0] + gx.x);
                    float g1 = sigmoidf_(acc[mi][ni][2 * p + 1] + gx.y);
                    if (is_reset) {
                        size_t hi = (size_t)row * HIDDEN + col;
                        float2 h = *(const float2*)&d_H[hi];
                        *(float2*)&d_RH[hi] = make_float2(g0 * h.x, g1 * h.y);
                    } else {
                        size_t ui = (size_t)row * HIDDEN + (col - HIDDEN);
                        *(float2*)&d_U[ui] = make_float2(g0, g1);
                    }
                }
            }
    } else {
        const int block_col = (blockIdx.x - nx) * BN;
        const int tt = t + 1;
        gemm_core(x + (size_t)tt * IN_DIM, T_SEQ * IN_DIM, Wg, 2 * HIDDEN, IN_DIM,
                  block_row, block_col, acc);
#pragma unroll
        for (int mi = 0; mi < 4; mi++)
#pragma unroll
            for (int ni = 0; ni < 4; ni++) {
                int row = block_row + wm * 64 + mi * 16 + (lane >> 2);
                int col = block_col + wn * 32 + ni * 8 + ((lane & 3) << 1);
                float b0 = bg[col], b1 = bg[col + 1];
                *(float2*)&d_Gx[(size_t)(row * T_SEQ + tt) * (2 * HIDDEN) + col] =
                    make_float2(acc[mi][ni][0] + b0, acc[mi][ni][1] + b1);
                *(float2*)&d_Gx[(size_t)((row + 8) * T_SEQ + tt) * (2 * HIDDEN) + col] =
                    make_float2(acc[mi][ni][2] + b0, acc[mi][ni][3] + b1);
            }
    }
}

// ---------------- fused cand kernel ----------------
// blocks with blockIdx.x <  nx : cand step t  = tanh(Cx_t + RH @ Wc_h); h = u*h+(1-u)*c
// blocks with blockIdx.x >= nx : precompute Cx chunk for t+1 = x_{t+1} @ Wc_x + bc
__global__ __launch_bounds__(256) void cand_fused_kernel(
    const float* __restrict__ x, const float* __restrict__ Wc,
    const float* __restrict__ bc, float* __restrict__ y, int t, int nx)
{
    float acc[4][4][4];
    EPI_COORDS();

    if ((int)blockIdx.x < nx) {
        const int block_col = blockIdx.x * BN;
        gemm_core(d_RH, HIDDEN, Wc + (size_t)IN_DIM * HIDDEN, HIDDEN, HIDDEN,
                  block_row, block_col, acc);
#pragma unroll
        for (int mi = 0; mi < 4; mi++)
#pragma unroll
            for (int ni = 0; ni < 4; ni++) {
                int row0 = block_row + wm * 64 + mi * 16 + (lane >> 2);
                int col  = block_col + wn * 32 + ni * 8 + ((lane & 3) << 1);
#pragma unroll
                for (int p = 0; p < 2; p++) {
                    int row = row0 + p * 8;
                    size_t hi = (size_t)row * HIDDEN + col;
                    float2 cx = *(const float2*)&d_Cx[(size_t)(row * T_SEQ + t) * HIDDEN + col];
                    float c0 = tanhf(acc[mi][ni][2 * p + 0] + cx.x);
                    float c1 = tanhf(acc[mi][ni][2 * p + 1] + cx.y);
                    float2 u = *(const float2*)&d_U[hi];
                    float2 h = *(const float2*)&d_H[hi];
                    float hn0 = u.x * h.x + (1.0f - u.x) * c0;
                    float hn1 = u.y * h.y + (1.0f - u.y) * c1;
                    *(float2*)&d_H[hi] = make_float2(hn0, hn1);
                    *(float2*)&y[(size_t)row * T_SEQ * HIDDEN + (size_t)t * HIDDEN + col] =
                        make_float2(hn0, hn1);
                }
            }
    } else {
        const int block_col = (blockIdx.x - nx) * BN;
        const int tt = t + 1;
        gemm_core(x + (size_t)tt * IN_DIM, T_SEQ * IN_DIM, Wc, HIDDEN, IN_DIM,
                  block_row, block_col, acc);
#pragma unroll
        for (int mi = 0; mi < 4; mi++)
#pragma unroll
            for (int ni = 0; ni < 4; ni++) {
                int row = block_row + wm * 64 + mi * 16 + (lane >> 2);
                int col = block_col + wn * 32 + ni * 8 + ((lane & 3) << 1);
                float b0 = bc[col], b1 = bc[col + 1];
                *(float2*)&d_Cx[(size_t)(row * T_SEQ + tt) * HIDDEN + col] =
                    make_float2(acc[mi][ni][0] + b0, acc[mi][ni][1] + b1);
                *(float2*)&d_Cx[(size_t)((row + 8) * T_SEQ + tt) * HIDDEN + col] =
                    make_float2(acc[mi][ni][2] + b0, acc[mi][ni][3] + b1);
            }
    }
}

// ---------------- launch ----------------
extern "C" void kernel_launch(void* const* d_in, const int* in_sizes, int n_in,
                              void* d_out, int out_size)
{
    const float* x  = (const float*)d_in[0];  // [B, T, D]
    const float* h0 = (const float*)d_in[1];  // [B, H]
    const float* Wg = (const float*)d_in[2];  // [D+H, 2H]
    const float* bg = (const float*)d_in[3];  // [2H]
    const float* Wc = (const float*)d_in[4];  // [D+H, H]
    const float* bc = (const float*)d_in[5];  // [H]
    float* y = (float*)d_out;                 // [B, T, H]

    cudaFuncSetAttribute(gate_fused_kernel, cudaFuncAttributeMaxDynamicSharedMemorySize, SMEM_BYTES);
    cudaFuncSetAttribute(cand_fused_kernel, cudaFuncAttributeMaxDynamicSharedMemorySize, SMEM_BYTES);

    // h <- coded_cords
    init_h_kernel<<<(BATCH * HIDDEN / 4) / 256, 256>>>(h0);

    const int NXG = 2 * HIDDEN / BN;   // 16 gate-step col blocks
    const int NXC = HIDDEN / BN;       // 8  cand-step col blocks
    const int MY  = BATCH / BM;        // 16 row blocks

    // prologue: precompute chunk t=0 only (nx=0 -> all blocks are pre-role, tt=0)
    gate_fused_kernel<<<dim3(NXG, MY), 256, SMEM_BYTES>>>(x, Wg, bg, -1, 0);
    cand_fused_kernel<<<dim3(NXC, MY), 256, SMEM_BYTES>>>(x, Wc, bc, y, -1, 0);

    // serial recurrence; each step also precomputes chunk t+1 in its spare blocks
    for (int t = 0; t < T_SEQ; t++) {
        int gx = NXG + (t < T_SEQ - 1 ? NXG : 0);
        gate_fused_kernel<<<dim3(gx, MY), 256, SMEM_BYTES>>>(x, Wg, bg, t, NXG);
        int cx = NXC + (t < T_SEQ - 1 ? NXC : 0);
        cand_fused_kernel<<<dim3(cx, MY), 256, SMEM_BYTES>>>(x, Wc, bc, y, t, NXC);
    }
}

// round 10
// speedup vs baseline: 1.2012x; 1.2012x over previous
#include <cuda_runtime.h>
#include <cstdint>
#include <cstddef>

#define T_SEQ   12
#define BATCH   2048
#define IN_DIM  512
#define HIDDEN  1024

// ---------------- scratch (no runtime allocation allowed) ----------------
__device__ float d_H [BATCH * HIDDEN];
__device__ float d_RH[BATCH * HIDDEN];
__device__ float d_U [BATCH * HIDDEN];
__device__ float d_Gx[(size_t)BATCH * T_SEQ * 2 * HIDDEN];
__device__ float d_Cx[(size_t)BATCH * T_SEQ * HIDDEN];

// ---------------- mma / cp.async helpers ----------------
__device__ __forceinline__ void mma_tf32(float c[4], const uint32_t a[4], const uint32_t b[2]) {
    asm volatile(
        "mma.sync.aligned.m16n8k8.row.col.f32.tf32.tf32.f32 "
        "{%0,%1,%2,%3}, {%4,%5,%6,%7}, {%8,%9}, {%0,%1,%2,%3};\n"
        : "+f"(c[0]), "+f"(c[1]), "+f"(c[2]), "+f"(c[3])
        : "r"(a[0]), "r"(a[1]), "r"(a[2]), "r"(a[3]), "r"(b[0]), "r"(b[1]));
}

__device__ __forceinline__ void cp_async16(uint32_t dst, const void* src) {
    asm volatile("cp.async.cg.shared.global [%0], [%1], 16;\n" :: "r"(dst), "l"(src));
}

// ---------------- GEMM core, templated on MI (warp M-tiles): BM = 32*MI ----------------
// 8 warps as 2 (M) x 4 (N). BN = 128 fixed, BK = 32, 256 threads.
// 3-stage cp.async ring, ONE barrier per K-slab, double-buffered register fragments.
#define BN 128
#define BK 32
#define NSTAGE 3
#define SA_STRIDE 36   // BK + 4
#define SB_STRIDE 136  // BN + 8
#define SB_ELEMS  (BK * SB_STRIDE)

#define SA_ELEMS_MI(MI)   (32 * (MI) * SA_STRIDE)
#define STAGE_ELEMS_MI(MI) (SA_ELEMS_MI(MI) + SB_ELEMS)
#define SMEM_BYTES_MI(MI) (NSTAGE * STAGE_ELEMS_MI(MI) * 4)
// MI=4: 107520 bytes   MI=2: 79872 bytes

template<int MI>
__device__ __forceinline__ void load_stage(
    uint32_t stage_addr,
    const float* __restrict__ A, int lda,
    const float* __restrict__ B, int ldb,
    int block_row, int block_col, int k0, int tid)
{
    const uint32_t sA_addr = stage_addr;
    const uint32_t sB_addr = stage_addr + SA_ELEMS_MI(MI) * 4;
#pragma unroll
    for (int i = 0; i < MI; i++) {           // 32*MI rows x 32 floats = 256*MI float4
        int idx = tid + i * 256;
        int r = idx >> 3, c = (idx & 7) << 2;
        cp_async16(sA_addr + (uint32_t)(r * SA_STRIDE + c) * 4,
                   A + (size_t)(block_row + r) * lda + k0 + c);
    }
#pragma unroll
    for (int i = 0; i < 4; i++) {            // 32 rows x 128 floats
        int idx = tid + i * 256;
        int r = idx >> 5, c = (idx & 31) << 2;
        cp_async16(sB_addr + (uint32_t)(r * SB_STRIDE + c) * 4,
                   B + (size_t)(k0 + r) * ldb + block_col + c);
    }
    asm volatile("cp.async.commit_group;\n" ::: "memory");
}

template<int MI>
__device__ __forceinline__ void load_frags(
    const uint32_t* __restrict__ cA, const uint32_t* __restrict__ cB, int kk,
    int lane, int wm, int wn,
    uint32_t (&af)[MI][4], uint32_t (&bf)[4][2])
{
#pragma unroll
    for (int mi = 0; mi < MI; mi++) {
        int rb = wm * (MI * 16) + mi * 16 + (lane >> 2);
        const uint32_t* p = cA + rb * SA_STRIDE + kk + (lane & 3);
        af[mi][0] = p[0];
        af[mi][1] = p[8 * SA_STRIDE];
        af[mi][2] = p[4];
        af[mi][3] = p[8 * SA_STRIDE + 4];
    }
#pragma unroll
    for (int ni = 0; ni < 4; ni++) {
        int cb = wn * 32 + ni * 8 + (lane >> 2);
        const uint32_t* p = cB + (kk + (lane & 3)) * SB_STRIDE + cb;
        bf[ni][0] = p[0];
        bf[ni][1] = p[4 * SB_STRIDE];
    }
}

template<int MI>
__device__ __forceinline__ void gemm_core(
    const float* __restrict__ A, int lda,
    const float* __restrict__ B, int ldb,
    int K, int block_row, int block_col,
    float (&acc)[MI][4][4])
{
    extern __shared__ uint32_t smem[];

    const int tid  = threadIdx.x;
    const int lane = tid & 31;
    const int warp = tid >> 5;
    const int wm   = warp & 1;
    const int wn   = warp >> 1;

    const uint32_t smem_base = (uint32_t)__cvta_generic_to_shared(smem);

#pragma unroll
    for (int mi = 0; mi < MI; mi++)
#pragma unroll
        for (int ni = 0; ni < 4; ni++)
#pragma unroll
            for (int r = 0; r < 4; r++) acc[mi][ni][r] = 0.0f;

    const int nsteps = K / BK;

    load_stage<MI>(smem_base, A, lda, B, ldb, block_row, block_col, 0, tid);
    load_stage<MI>(smem_base + STAGE_ELEMS_MI(MI) * 4, A, lda, B, ldb,
                   block_row, block_col, BK, tid);

    int mbuf = 0, lbuf = 2;

    for (int s = 0; s < nsteps; s++) {
        if (s == nsteps - 1)
            asm volatile("cp.async.wait_group 0;\n" ::: "memory");
        else
            asm volatile("cp.async.wait_group 1;\n" ::: "memory");
        __syncthreads();

        if (s + 2 < nsteps) {
            load_stage<MI>(smem_base + (uint32_t)lbuf * STAGE_ELEMS_MI(MI) * 4,
                           A, lda, B, ldb, block_row, block_col, (s + 2) * BK, tid);
        }
        lbuf = (lbuf == NSTAGE - 1) ? 0 : lbuf + 1;

        const uint32_t* cA = smem + (size_t)mbuf * STAGE_ELEMS_MI(MI);
        const uint32_t* cB = cA + SA_ELEMS_MI(MI);
        mbuf = (mbuf == NSTAGE - 1) ? 0 : mbuf + 1;

        // double-buffered register fragments: LDS for ks+1 issue before MMAs of ks
        uint32_t af[2][MI][4], bf[2][4][2];
        load_frags<MI>(cA, cB, 0, lane, wm, wn, af[0], bf[0]);
#pragma unroll
        for (int ks = 0; ks < 4; ks++) {
            if (ks < 3)
                load_frags<MI>(cA, cB, (ks + 1) * 8, lane, wm, wn,
                               af[(ks + 1) & 1], bf[(ks + 1) & 1]);
            const int cb_ = ks & 1;
#pragma unroll
            for (int mi = 0; mi < MI; mi++)
#pragma unroll
                for (int ni = 0; ni < 4; ni++)
                    mma_tf32(acc[mi][ni], af[cb_][mi], bf[cb_][ni]);
        }
        // no trailing barrier (3-stage ring)
    }
}

__device__ __forceinline__ float sigmoidf_(float x) { return 1.0f / (1.0f + expf(-x)); }

// ---------------- kernel: h <- coded_cords ----------------
__global__ __launch_bounds__(256) void init_h_kernel(const float* __restrict__ src) {
    size_t i = (size_t)blockIdx.x * 256 + threadIdx.x;
    ((float4*)d_H)[i] = ((const float4*)src)[i];
}

// ---------------- kernel: Gx = X @ Wg[0:512,:] + bg  (MI=4) ----------------
__global__ __launch_bounds__(256, 2) void pre_gate_kernel(
    const float* __restrict__ x, const float* __restrict__ Wg, const float* __restrict__ bg)
{
    float acc[4][4][4];
    const int lane = threadIdx.x & 31, warp = threadIdx.x >> 5;
    const int wm = warp & 1, wn = warp >> 1;
    const int block_row = blockIdx.y * 128, block_col = blockIdx.x * BN;
    gemm_core<4>(x, IN_DIM, Wg, 2 * HIDDEN, IN_DIM, block_row, block_col, acc);
#pragma unroll
    for (int mi = 0; mi < 4; mi++)
#pragma unroll
        for (int ni = 0; ni < 4; ni++) {
            int row = block_row + wm * 64 + mi * 16 + (lane >> 2);
            int col = block_col + wn * 32 + ni * 8 + ((lane & 3) << 1);
            float b0 = bg[col], b1 = bg[col + 1];
            *(float2*)&d_Gx[(size_t)row * (2 * HIDDEN) + col] =
                make_float2(acc[mi][ni][0] + b0, acc[mi][ni][1] + b1);
            *(float2*)&d_Gx[(size_t)(row + 8) * (2 * HIDDEN) + col] =
                make_float2(acc[mi][ni][2] + b0, acc[mi][ni][3] + b1);
        }
}

// ---------------- kernel: Cx = X @ Wc[0:512,:] + bc  (MI=4) ----------------
__global__ __launch_bounds__(256, 2) void pre_cand_kernel(
    const float* __restrict__ x, const float* __restrict__ Wc, const float* __restrict__ bc)
{
    float acc[4][4][4];
    const int lane = threadIdx.x & 31, warp = threadIdx.x >> 5;
    const int wm = warp & 1, wn = warp >> 1;
    const int block_row = blockIdx.y * 128, block_col = blockIdx.x * BN;
    gemm_core<4>(x, IN_DIM, Wc, HIDDEN, IN_DIM, block_row, block_col, acc);
#pragma unroll
    for (int mi = 0; mi < 4; mi++)
#pragma unroll
        for (int ni = 0; ni < 4; ni++) {
            int row = block_row + wm * 64 + mi * 16 + (lane >> 2);
            int col = block_col + wn * 32 + ni * 8 + ((lane & 3) << 1);
            float b0 = bc[col], b1 = bc[col + 1];
            *(float2*)&d_Cx[(size_t)row * HIDDEN + col] =
                make_float2(acc[mi][ni][0] + b0, acc[mi][ni][1] + b1);
            *(float2*)&d_Cx[(size_t)(row + 8) * HIDDEN + col] =
                make_float2(acc[mi][ni][2] + b0, acc[mi][ni][3] + b1);
        }
}

// ---------------- gate step (MI=4): sigmoid(Gx_t + H @ Wg_h) -> RH, U ----------------
__global__ __launch_bounds__(256, 2) void gate_step_kernel(const float* __restrict__ Wg, int t)
{
    float acc[4][4][4];
    const int lane = threadIdx.x & 31, warp = threadIdx.x >> 5;
    const int wm = warp & 1, wn = warp >> 1;
    const int block_row = blockIdx.y * 128, block_col = blockIdx.x * BN;
    gemm_core<4>(d_H, HIDDEN, Wg + (size_t)IN_DIM * 2 * HIDDEN, 2 * HIDDEN, HIDDEN,
                 block_row, block_col, acc);
    const bool is_reset = (block_col < HIDDEN);   // uniform per block
#pragma unroll
    for (int mi = 0; mi < 4; mi++)
#pragma unroll
        for (int ni = 0; ni < 4; ni++) {
            int row0 = block_row + wm * 64 + mi * 16 + (lane >> 2);
            int col  = block_col + wn * 32 + ni * 8 + ((lane & 3) << 1);
#pragma unroll
            for (int p = 0; p < 2; p++) {
                int row = row0 + p * 8;
                float2 gx = *(const float2*)&d_Gx[(size_t)(row * T_SEQ + t) * (2 * HIDDEN) + col];
                float g0 = sigmoidf_(acc[mi][ni][2 * p + 0] + gx.x);
                float g1 = sigmoidf_(acc[mi][ni][2 * p + 1] + gx.y);
                if (is_reset) {
                    size_t hi = (size_t)row * HIDDEN + col;
                    float2 h = *(const float2*)&d_H[hi];
                    *(float2*)&d_RH[hi] = make_float2(g0 * h.x, g1 * h.y);
                } else {
                    size_t ui = (size_t)row * HIDDEN + (col - HIDDEN);
                    *(float2*)&d_U[ui] = make_float2(g0, g1);
                }
            }
        }
}

// ---------------- cand step (MI=2, BM=64): full-chip grid (8,32) ----------------
__global__ __launch_bounds__(256, 2) void cand_step_kernel(
    const float* __restrict__ Wc, float* __restrict__ y, int t)
{
    float acc[2][4][4];
    const int lane = threadIdx.x & 31, warp = threadIdx.x >> 5;
    const int wm = warp & 1, wn = warp >> 1;
    const int block_row = blockIdx.y * 64, block_col = blockIdx.x * BN;
    gemm_core<2>(d_RH, HIDDEN, Wc + (size_t)IN_DIM * HIDDEN, HIDDEN, HIDDEN,
                 block_row, block_col, acc);
#pragma unroll
    for (int mi = 0; mi < 2; mi++)
#pragma unroll
        for (int ni = 0; ni < 4; ni++) {
            int row0 = block_row + wm * 32 + mi * 16 + (lane >> 2);
            int col  = block_col + wn * 32 + ni * 8 + ((lane & 3) << 1);
#pragma unroll
            for (int p = 0; p < 2; p++) {
                int row = row0 + p * 8;
                size_t hi = (size_t)row * HIDDEN + col;
                float2 cx = *(const float2*)&d_Cx[(size_t)(row * T_SEQ + t) * HIDDEN + col];
                float c0 = tanhf(acc[mi][ni][2 * p + 0] + cx.x);
                float c1 = tanhf(acc[mi][ni][2 * p + 1] + cx.y);
                float2 u = *(const float2*)&d_U[hi];
                float2 h = *(const float2*)&d_H[hi];
                float hn0 = u.x * h.x + (1.0f - u.x) * c0;
                float hn1 = u.y * h.y + (1.0f - u.y) * c1;
                *(float2*)&d_H[hi] = make_float2(hn0, hn1);
                *(float2*)&y[(size_t)row * T_SEQ * HIDDEN + (size_t)t * HIDDEN + col] =
                    make_float2(hn0, hn1);
            }
        }
}

// ---------------- launch ----------------
extern "C" void kernel_launch(void* const* d_in, const int* in_sizes, int n_in,
                              void* d_out, int out_size)
{
    const float* x  = (const float*)d_in[0];  // [B, T, D]
    const float* h0 = (const float*)d_in[1];  // [B, H]
    const float* Wg = (const float*)d_in[2];  // [D+H, 2H]
    const float* bg = (const float*)d_in[3];  // [2H]
    const float* Wc = (const float*)d_in[4];  // [D+H, H]
    const float* bc = (const float*)d_in[5];  // [H]
    float* y = (float*)d_out;                 // [B, T, H]

    const int S4 = SMEM_BYTES_MI(4);   // 107520
    const int S2 = SMEM_BYTES_MI(2);   // 79872

    cudaFuncSetAttribute(pre_gate_kernel,  cudaFuncAttributeMaxDynamicSharedMemorySize, S4);
    cudaFuncSetAttribute(pre_cand_kernel,  cudaFuncAttributeMaxDynamicSharedMemorySize, S4);
    cudaFuncSetAttribute(gate_step_kernel, cudaFuncAttributeMaxDynamicSharedMemorySize, S4);
    cudaFuncSetAttribute(cand_step_kernel, cudaFuncAttributeMaxDynamicSharedMemorySize, S2);

    init_h_kernel<<<(BATCH * HIDDEN / 4) / 256, 256>>>(h0);

    // Precompute x-dependent halves (fully parallel over B*T)
    pre_gate_kernel<<<dim3(2 * HIDDEN / BN, (BATCH * T_SEQ) / 128), 256, S4>>>(x, Wg, bg);
    pre_cand_kernel<<<dim3(HIDDEN / BN, (BATCH * T_SEQ) / 128), 256, S4>>>(x, Wc, bc);

    // Serial recurrence
    for (int t = 0; t < T_SEQ; t++) {
        gate_step_kernel<<<dim3(2 * HIDDEN / BN, BATCH / 128), 256, S4>>>(Wg, t);   // (16,16)
        cand_step_kernel<<<dim3(HIDDEN / BN, BATCH / 64), 256, S2>>>(Wc, y, t);     // (8,32)
    }
}

// round 11
// speedup vs baseline: 1.2582x; 1.0475x over previous
#include <cuda_runtime.h>
#include <cstdint>
#include <cstddef>

#define T_SEQ   12
#define BATCH   2048
#define IN_DIM  512
#define HIDDEN  1024

// ---------------- scratch (no runtime allocation allowed) ----------------
__device__ float d_H [BATCH * HIDDEN];
__device__ float d_RH[BATCH * HIDDEN];
__device__ float d_U [BATCH * HIDDEN];
__device__ float d_Gx[(size_t)BATCH * T_SEQ * 2 * HIDDEN];
__device__ float d_Cx[(size_t)BATCH * T_SEQ * HIDDEN];

// ---------------- mma / cp.async helpers ----------------
__device__ __forceinline__ void mma_tf32(float c[4], const uint32_t a[4], const uint32_t b[2]) {
    asm volatile(
        "mma.sync.aligned.m16n8k8.row.col.f32.tf32.tf32.f32 "
        "{%0,%1,%2,%3}, {%4,%5,%6,%7}, {%8,%9}, {%0,%1,%2,%3};\n"
        : "+f"(c[0]), "+f"(c[1]), "+f"(c[2]), "+f"(c[3])
        : "r"(a[0]), "r"(a[1]), "r"(a[2]), "r"(a[3]), "r"(b[0]), "r"(b[1]));
}

__device__ __forceinline__ void cp_async16(uint32_t dst, const void* src) {
    asm volatile("cp.async.cg.shared.global [%0], [%1], 16;\n" :: "r"(dst), "l"(src));
}

// ---------------- GEMM core, templated on MI (BM = 32*MI) and NSTAGE ----------------
// 8 warps as 2 (M) x 4 (N). BN = 128, BK = 32, 256 threads.
#define BN 128
#define BK 32
#define SA_STRIDE 36   // BK + 4
#define SB_STRIDE 136  // BN + 8
#define SB_ELEMS  (BK * SB_STRIDE)

#define SA_ELEMS_MI(MI)    (32 * (MI) * SA_STRIDE)
#define STAGE_ELEMS_MI(MI) (SA_ELEMS_MI(MI) + SB_ELEMS)
#define SMEM_BYTES(MI, NS) ((NS) * STAGE_ELEMS_MI(MI) * 4)
// MI=4,NS=3: 107520   MI=2,NS=2: 53248

template<int MI>
__device__ __forceinline__ void load_stage(
    uint32_t stage_addr,
    const float* __restrict__ A, int lda,
    const float* __restrict__ B, int ldb,
    int block_row, int block_col, int k0, int tid)
{
    const uint32_t sA_addr = stage_addr;
    const uint32_t sB_addr = stage_addr + SA_ELEMS_MI(MI) * 4;
#pragma unroll
    for (int i = 0; i < MI; i++) {           // 32*MI rows x 32 floats
        int idx = tid + i * 256;
        int r = idx >> 3, c = (idx & 7) << 2;
        cp_async16(sA_addr + (uint32_t)(r * SA_STRIDE + c) * 4,
                   A + (size_t)(block_row + r) * lda + k0 + c);
    }
#pragma unroll
    for (int i = 0; i < 4; i++) {            // 32 rows x 128 floats
        int idx = tid + i * 256;
        int r = idx >> 5, c = (idx & 31) << 2;
        cp_async16(sB_addr + (uint32_t)(r * SB_STRIDE + c) * 4,
                   B + (size_t)(k0 + r) * ldb + block_col + c);
    }
    asm volatile("cp.async.commit_group;\n" ::: "memory");
}

template<int MI>
__device__ __forceinline__ void compute_slab(
    const uint32_t* __restrict__ cA, const uint32_t* __restrict__ cB,
    int lane, int wm, int wn, float (&acc)[MI][4][4])
{
#pragma unroll
    for (int ks = 0; ks < 4; ks++) {
        const int kk = ks * 8;
        uint32_t af[MI][4], bf[4][2];
#pragma unroll
        for (int mi = 0; mi < MI; mi++) {
            int rb = wm * (MI * 16) + mi * 16 + (lane >> 2);
            const uint32_t* p = cA + rb * SA_STRIDE + kk + (lane & 3);
            af[mi][0] = p[0];
            af[mi][1] = p[8 * SA_STRIDE];
            af[mi][2] = p[4];
            af[mi][3] = p[8 * SA_STRIDE + 4];
        }
#pragma unroll
        for (int ni = 0; ni < 4; ni++) {
            int cb = wn * 32 + ni * 8 + (lane >> 2);
            const uint32_t* p = cB + (kk + (lane & 3)) * SB_STRIDE + cb;
            bf[ni][0] = p[0];
            bf[ni][1] = p[4 * SB_STRIDE];
        }
#pragma unroll
        for (int mi = 0; mi < MI; mi++)
#pragma unroll
            for (int ni = 0; ni < 4; ni++)
                mma_tf32(acc[mi][ni], af[mi], bf[ni]);
    }
}

template<int MI, int NS>
__device__ __forceinline__ void gemm_core(
    const float* __restrict__ A, int lda,
    const float* __restrict__ B, int ldb,
    int K, int block_row, int block_col,
    float (&acc)[MI][4][4])
{
    extern __shared__ uint32_t smem[];

    const int tid  = threadIdx.x;
    const int lane = tid & 31;
    const int warp = tid >> 5;
    const int wm   = warp & 1;
    const int wn   = warp >> 1;

    const uint32_t smem_base = (uint32_t)__cvta_generic_to_shared(smem);

#pragma unroll
    for (int mi = 0; mi < MI; mi++)
#pragma unroll
        for (int ni = 0; ni < 4; ni++)
#pragma unroll
            for (int r = 0; r < 4; r++) acc[mi][ni][r] = 0.0f;

    const int nsteps = K / BK;

    if (NS == 3) {
        // 3-stage ring, one barrier per slab
        load_stage<MI>(smem_base, A, lda, B, ldb, block_row, block_col, 0, tid);
        load_stage<MI>(smem_base + STAGE_ELEMS_MI(MI) * 4, A, lda, B, ldb,
                       block_row, block_col, BK, tid);
        int mbuf = 0, lbuf = 2;
        for (int s = 0; s < nsteps; s++) {
            if (s == nsteps - 1)
                asm volatile("cp.async.wait_group 0;\n" ::: "memory");
            else
                asm volatile("cp.async.wait_group 1;\n" ::: "memory");
            __syncthreads();
            if (s + 2 < nsteps)
                load_stage<MI>(smem_base + (uint32_t)lbuf * STAGE_ELEMS_MI(MI) * 4,
                               A, lda, B, ldb, block_row, block_col, (s + 2) * BK, tid);
            lbuf = (lbuf == 2) ? 0 : lbuf + 1;
            const uint32_t* cA = smem + (size_t)mbuf * STAGE_ELEMS_MI(MI);
            mbuf = (mbuf == 2) ? 0 : mbuf + 1;
            compute_slab<MI>(cA, cA + SA_ELEMS_MI(MI), lane, wm, wn, acc);
        }
    } else {
        // 2-stage double buffer, two barriers per slab
        load_stage<MI>(smem_base, A, lda, B, ldb, block_row, block_col, 0, tid);
        for (int s = 0; s < nsteps; s++) {
            const int cur = s & 1;
            if (s + 1 < nsteps) {
                load_stage<MI>(smem_base + (uint32_t)((s + 1) & 1) * STAGE_ELEMS_MI(MI) * 4,
                               A, lda, B, ldb, block_row, block_col, (s + 1) * BK, tid);
                asm volatile("cp.async.wait_group 1;\n" ::: "memory");
            } else {
                asm volatile("cp.async.wait_group 0;\n" ::: "memory");
            }
            __syncthreads();
            const uint32_t* cA = smem + (size_t)cur * STAGE_ELEMS_MI(MI);
            compute_slab<MI>(cA, cA + SA_ELEMS_MI(MI), lane, wm, wn, acc);
            __syncthreads();
        }
    }
}

__device__ __forceinline__ float sigmoidf_(float x) { return 1.0f / (1.0f + expf(-x)); }

// ---------------- kernel: h <- coded_cords ----------------
__global__ __launch_bounds__(256) void init_h_kernel(const float* __restrict__ src) {
    size_t i = (size_t)blockIdx.x * 256 + threadIdx.x;
    ((float4*)d_H)[i] = ((const float4*)src)[i];
}

// ---------------- precompute kernels (MI=4, NS=3, BM=128) ----------------
__global__ __launch_bounds__(256, 2) void pre_gate_kernel(
    const float* __restrict__ x, const float* __restrict__ Wg, const float* __restrict__ bg)
{
    float acc[4][4][4];
    const int lane = threadIdx.x & 31, warp = threadIdx.x >> 5;
    const int wm = warp & 1, wn = warp >> 1;
    const int block_row = blockIdx.y * 128, block_col = blockIdx.x * BN;
    gemm_core<4, 3>(x, IN_DIM, Wg, 2 * HIDDEN, IN_DIM, block_row, block_col, acc);
#pragma unroll
    for (int mi = 0; mi < 4; mi++)
#pragma unroll
        for (int ni = 0; ni < 4; ni++) {
            int row = block_row + wm * 64 + mi * 16 + (lane >> 2);
            int col = block_col + wn * 32 + ni * 8 + ((lane & 3) << 1);
            float b0 = bg[col], b1 = bg[col + 1];
            *(float2*)&d_Gx[(size_t)row * (2 * HIDDEN) + col] =
                make_float2(acc[mi][ni][0] + b0, acc[mi][ni][1] + b1);
            *(float2*)&d_Gx[(size_t)(row + 8) * (2 * HIDDEN) + col] =
                make_float2(acc[mi][ni][2] + b0, acc[mi][ni][3] + b1);
        }
}

__global__ __launch_bounds__(256, 2) void pre_cand_kernel(
    const float* __restrict__ x, const float* __restrict__ Wc, const float* __restrict__ bc)
{
    float acc[4][4][4];
    const int lane = threadIdx.x & 31, warp = threadIdx.x >> 5;
    const int wm = warp & 1, wn = warp >> 1;
    const int block_row = blockIdx.y * 128, block_col = blockIdx.x * BN;
    gemm_core<4, 3>(x, IN_DIM, Wc, HIDDEN, IN_DIM, block_row, block_col, acc);
#pragma unroll
    for (int mi = 0; mi < 4; mi++)
#pragma unroll
        for (int ni = 0; ni < 4; ni++) {
            int row = block_row + wm * 64 + mi * 16 + (lane >> 2);
            int col = block_col + wn * 32 + ni * 8 + ((lane & 3) << 1);
            float b0 = bc[col], b1 = bc[col + 1];
            *(float2*)&d_Cx[(size_t)row * HIDDEN + col] =
                make_float2(acc[mi][ni][0] + b0, acc[mi][ni][1] + b1);
            *(float2*)&d_Cx[(size_t)(row + 8) * HIDDEN + col] =
                make_float2(acc[mi][ni][2] + b0, acc[mi][ni][3] + b1);
        }
}

// ---------------- gate step (MI=2, NS=2, BM=64): grid (16,32) = 512 blocks ----------------
__global__ __launch_bounds__(256) void gate_step_kernel(const float* __restrict__ Wg, int t)
{
    float acc[2][4][4];
    const int lane = threadIdx.x & 31, warp = threadIdx.x >> 5;
    const int wm = warp & 1, wn = warp >> 1;
    const int block_row = blockIdx.y * 64, block_col = blockIdx.x * BN;
    gemm_core<2, 2>(d_H, HIDDEN, Wg + (size_t)IN_DIM * 2 * HIDDEN, 2 * HIDDEN, HIDDEN,
                    block_row, block_col, acc);
    const bool is_reset = (block_col < HIDDEN);   // uniform per block
#pragma unroll
    for (int mi = 0; mi < 2; mi++)
#pragma unroll
        for (int ni = 0; ni < 4; ni++) {
            int row0 = block_row + wm * 32 + mi * 16 + (lane >> 2);
            int col  = block_col + wn * 32 + ni * 8 + ((lane & 3) << 1);
#pragma unroll
            for (int p = 0; p < 2; p++) {
                int row = row0 + p * 8;
                float2 gx = *(const float2*)&d_Gx[(size_t)(row * T_SEQ + t) * (2 * HIDDEN) + col];
                float g0 = sigmoidf_(acc[mi][ni][2 * p + 0] + gx.x);
                float g1 = sigmoidf_(acc[mi][ni][2 * p + 1] + gx.y);
                if (is_reset) {
                    size_t hi = (size_t)row * HIDDEN + col;
                    float2 h = *(const float2*)&d_H[hi];
                    *(float2*)&d_RH[hi] = make_float2(g0 * h.x, g1 * h.y);
                } else {
                    size_t ui = (size_t)row * HIDDEN + (col - HIDDEN);
                    *(float2*)&d_U[ui] = make_float2(g0, g1);
                }
            }
        }
}

// ---------------- cand step (MI=2, NS=2, BM=64): grid (8,32) = 256 blocks ----------------
__global__ __launch_bounds__(256) void cand_step_kernel(
    const float* __restrict__ Wc, float* __restrict__ y, int t)
{
    float acc[2][4][4];
    const int lane = threadIdx.x & 31, warp = threadIdx.x >> 5;
    const int wm = warp & 1, wn = warp >> 1;
    const int block_row = blockIdx.y * 64, block_col = blockIdx.x * BN;
    gemm_core<2, 2>(d_RH, HIDDEN, Wc + (size_t)IN_DIM * HIDDEN, HIDDEN, HIDDEN,
                    block_row, block_col, acc);
#pragma unroll
    for (int mi = 0; mi < 2; mi++)
#pragma unroll
        for (int ni = 0; ni < 4; ni++) {
            int row0 = block_row + wm * 32 + mi * 16 + (lane >> 2);
            int col  = block_col + wn * 32 + ni * 8 + ((lane & 3) << 1);
#pragma unroll
            for (int p = 0; p < 2; p++) {
                int row = row0 + p * 8;
                size_t hi = (size_t)row * HIDDEN + col;
                float2 cx = *(const float2*)&d_Cx[(size_t)(row * T_SEQ + t) * HIDDEN + col];
                float c0 = tanhf(acc[mi][ni][2 * p + 0] + cx.x);
                float c1 = tanhf(acc[mi][ni][2 * p + 1] + cx.y);
                float2 u = *(const float2*)&d_U[hi];
                float2 h = *(const float2*)&d_H[hi];
                float hn0 = u.x * h.x + (1.0f - u.x) * c0;
                float hn1 = u.y * h.y + (1.0f - u.y) * c1;
                *(float2*)&d_H[hi] = make_float2(hn0, hn1);
                *(float2*)&y[(size_t)row * T_SEQ * HIDDEN + (size_t)t * HIDDEN + col] =
                    make_float2(hn0, hn1);
            }
        }
}

// ---------------- launch ----------------
extern "C" void kernel_launch(void* const* d_in, const int* in_sizes, int n_in,
                              void* d_out, int out_size)
{
    const float* x  = (const float*)d_in[0];  // [B, T, D]
    const float* h0 = (const float*)d_in[1];  // [B, H]
    const float* Wg = (const float*)d_in[2];  // [D+H, 2H]
    const float* bg = (const float*)d_in[3];  // [2H]
    const float* Wc = (const float*)d_in[4];  // [D+H, H]
    const float* bc = (const float*)d_in[5];  // [H]
    float* y = (float*)d_out;                 // [B, T, H]

    const int S_PRE  = SMEM_BYTES(4, 3);   // 107520
    const int S_STEP = SMEM_BYTES(2, 2);   // 53248

    cudaFuncSetAttribute(pre_gate_kernel,  cudaFuncAttributeMaxDynamicSharedMemorySize, S_PRE);
    cudaFuncSetAttribute(pre_cand_kernel,  cudaFuncAttributeMaxDynamicSharedMemorySize, S_PRE);
    cudaFuncSetAttribute(gate_step_kernel, cudaFuncAttributeMaxDynamicSharedMemorySize, S_STEP);
    cudaFuncSetAttribute(cand_step_kernel, cudaFuncAttributeMaxDynamicSharedMemorySize, S_STEP);

    init_h_kernel<<<(BATCH * HIDDEN / 4) / 256, 256>>>(h0);

    // Precompute x-dependent halves (fully parallel over B*T)
    pre_gate_kernel<<<dim3(2 * HIDDEN / BN, (BATCH * T_SEQ) / 128), 256, S_PRE>>>(x, Wg, bg);
    pre_cand_kernel<<<dim3(HIDDEN / BN, (BATCH * T_SEQ) / 128), 256, S_PRE>>>(x, Wc, bc);

    // Serial recurrence
    for (int t = 0; t < T_SEQ; t++) {
        gate_step_kernel<<<dim3(2 * HIDDEN / BN, BATCH / 64), 256, S_STEP>>>(Wg, t);   // (16,32)
        cand_step_kernel<<<dim3(HIDDEN / BN, BATCH / 64), 256, S_STEP>>>(Wc, y, t);    // (8,32)
    }
}

// round 13
// speedup vs baseline: 1.2669x; 1.0069x over previous
#include <cuda_runtime.h>
#include <cstdint>
#include <cstddef>

#define T_SEQ   12
#define BATCH   2048
#define IN_DIM  512
#define HIDDEN  1024

// ---------------- scratch (no runtime allocation allowed) ----------------
__device__ float d_H [BATCH * HIDDEN];
__device__ float d_RH[BATCH * HIDDEN];
__device__ float d_U [BATCH * HIDDEN];
__device__ float d_Gx[(size_t)BATCH * T_SEQ * 2 * HIDDEN];
__device__ float d_Cx[(size_t)BATCH * T_SEQ * HIDDEN];

// ---------------- mma / cp.async helpers ----------------
__device__ __forceinline__ void mma_tf32(float c[4], const uint32_t a[4], const uint32_t b[2]) {
    asm volatile(
        "mma.sync.aligned.m16n8k8.row.col.f32.tf32.tf32.f32 "
        "{%0,%1,%2,%3}, {%4,%5,%6,%7}, {%8,%9}, {%0,%1,%2,%3};\n"
        : "+f"(c[0]), "+f"(c[1]), "+f"(c[2]), "+f"(c[3])
        : "r"(a[0]), "r"(a[1]), "r"(a[2]), "r"(a[3]), "r"(b[0]), "r"(b[1]));
}

__device__ __forceinline__ void cp_async16(uint32_t dst, const void* src) {
    asm volatile("cp.async.cg.shared.global [%0], [%1], 16;\n" :: "r"(dst), "l"(src));
}

// ---------------- GEMM core, templated on MI (BM = 32*MI) and NSTAGE ----------------
// 8 warps as 2 (M) x 4 (N). BN = 128, BK = 32, 256 threads.
#define BN 128
#define BK 32
#define SA_STRIDE 36   // BK + 4
#define SB_STRIDE 136  // BN + 8
#define SB_ELEMS  (BK * SB_STRIDE)

#define SA_ELEMS_MI(MI)    (32 * (MI) * SA_STRIDE)
#define STAGE_ELEMS_MI(MI) (SA_ELEMS_MI(MI) + SB_ELEMS)
#define SMEM_BYTES(MI, NS) ((NS) * STAGE_ELEMS_MI(MI) * 4)
// MI=4,NS=3: 107520   MI=2,NS=2: 53248

template<int MI>
__device__ __forceinline__ void load_stage(
    uint32_t stage_addr,
    const float* __restrict__ A, int lda,
    const float* __restrict__ B, int ldb,
    int block_row, int block_col, int k0, int tid)
{
    const uint32_t sA_addr = stage_addr;
    const uint32_t sB_addr = stage_addr + SA_ELEMS_MI(MI) * 4;
#pragma unroll
    for (int i = 0; i < MI; i++) {           // 32*MI rows x 32 floats
        int idx = tid + i * 256;
        int r = idx >> 3, c = (idx & 7) << 2;
        cp_async16(sA_addr + (uint32_t)(r * SA_STRIDE + c) * 4,
                   A + (size_t)(block_row + r) * lda + k0 + c);
    }
#pragma unroll
    for (int i = 0; i < 4; i++) {            // 32 rows x 128 floats
        int idx = tid + i * 256;
        int r = idx >> 5, c = (idx & 31) << 2;
        cp_async16(sB_addr + (uint32_t)(r * SB_STRIDE + c) * 4,
                   B + (size_t)(k0 + r) * ldb + block_col + c);
    }
    asm volatile("cp.async.commit_group;\n" ::: "memory");
}

template<int MI>
__device__ __forceinline__ void compute_slab(
    const uint32_t* __restrict__ cA, const uint32_t* __restrict__ cB,
    int lane, int wm, int wn, float (&acc)[MI][4][4])
{
#pragma unroll
    for (int ks = 0; ks < 4; ks++) {
        const int kk = ks * 8;
        uint32_t af[MI][4], bf[4][2];
#pragma unroll
        for (int mi = 0; mi < MI; mi++) {
            int rb = wm * (MI * 16) + mi * 16 + (lane >> 2);
            const uint32_t* p = cA + rb * SA_STRIDE + kk + (lane & 3);
            af[mi][0] = p[0];
            af[mi][1] = p[8 * SA_STRIDE];
            af[mi][2] = p[4];
            af[mi][3] = p[8 * SA_STRIDE + 4];
        }
#pragma unroll
        for (int ni = 0; ni < 4; ni++) {
            int cb = wn * 32 + ni * 8 + (lane >> 2);
            const uint32_t* p = cB + (kk + (lane & 3)) * SB_STRIDE + cb;
            bf[ni][0] = p[0];
            bf[ni][1] = p[4 * SB_STRIDE];
        }
#pragma unroll
        for (int mi = 0; mi < MI; mi++)
#pragma unroll
            for (int ni = 0; ni < 4; ni++)
                mma_tf32(acc[mi][ni], af[mi], bf[ni]);
    }
}

template<int MI, int NS>
__device__ __forceinline__ void gemm_core(
    const float* __restrict__ A, int lda,
    const float* __restrict__ B, int ldb,
    int K, int block_row, int block_col,
    float (&acc)[MI][4][4])
{
    extern __shared__ uint32_t smem[];

    const int tid  = threadIdx.x;
    const int lane = tid & 31;
    const int warp = tid >> 5;
    const int wm   = warp & 1;
    const int wn   = warp >> 1;

    const uint32_t smem_base = (uint32_t)__cvta_generic_to_shared(smem);

#pragma unroll
    for (int mi = 0; mi < MI; mi++)
#pragma unroll
        for (int ni = 0; ni < 4; ni++)
#pragma unroll
            for (int r = 0; r < 4; r++) acc[mi][ni][r] = 0.0f;

    const int nsteps = K / BK;

    if (NS == 3) {
        load_stage<MI>(smem_base, A, lda, B, ldb, block_row, block_col, 0, tid);
        load_stage<MI>(smem_base + STAGE_ELEMS_MI(MI) * 4, A, lda, B, ldb,
                       block_row, block_col, BK, tid);
        int mbuf = 0, lbuf = 2;
        for (int s = 0; s < nsteps; s++) {
            if (s == nsteps - 1)
                asm volatile("cp.async.wait_group 0;\n" ::: "memory");
            else
                asm volatile("cp.async.wait_group 1;\n" ::: "memory");
            __syncthreads();
            if (s + 2 < nsteps)
                load_stage<MI>(smem_base + (uint32_t)lbuf * STAGE_ELEMS_MI(MI) * 4,
                               A, lda, B, ldb, block_row, block_col, (s + 2) * BK, tid);
            lbuf = (lbuf == 2) ? 0 : lbuf + 1;
            const uint32_t* cA = smem + (size_t)mbuf * STAGE_ELEMS_MI(MI);
            mbuf = (mbuf == 2) ? 0 : mbuf + 1;
            compute_slab<MI>(cA, cA + SA_ELEMS_MI(MI), lane, wm, wn, acc);
        }
    } else {
        load_stage<MI>(smem_base, A, lda, B, ldb, block_row, block_col, 0, tid);
        for (int s = 0; s < nsteps; s++) {
            const int cur = s & 1;
            if (s + 1 < nsteps) {
                load_stage<MI>(smem_base + (uint32_t)((s + 1) & 1) * STAGE_ELEMS_MI(MI) * 4,
                               A, lda, B, ldb, block_row, block_col, (s + 1) * BK, tid);
                asm volatile("cp.async.wait_group 1;\n" ::: "memory");
            } else {
                asm volatile("cp.async.wait_group 0;\n" ::: "memory");
            }
            __syncthreads();
            const uint32_t* cA = smem + (size_t)cur * STAGE_ELEMS_MI(MI);
            compute_slab<MI>(cA, cA + SA_ELEMS_MI(MI), lane, wm, wn, acc);
            __syncthreads();
        }
    }
}

__device__ __forceinline__ float sigmoidf_(float x) { return 1.0f / (1.0f + expf(-x)); }

// ---------------- kernel: h <- coded_cords ----------------
__global__ __launch_bounds__(256) void init_h_kernel(const float* __restrict__ src) {
    size_t i = (size_t)blockIdx.x * 256 + threadIdx.x;
    ((float4*)d_H)[i] = ((const float4*)src)[i];
}

// ---------------- per-timestep precompute chunks (MI=4, NS=3, BM=128) ----------------
// Gx[:, t, :] = x[:, t, :] @ Wg[0:512, :] + bg     (M = BATCH rows over batch)
__global__ __launch_bounds__(256, 2) void pre_gate_t_kernel(
    const float* __restrict__ x, const float* __restrict__ Wg,
    const float* __restrict__ bg, int t)
{
    float acc[4][4][4];
    const int lane = threadIdx.x & 31, warp = threadIdx.x >> 5;
    const int wm = warp & 1, wn = warp >> 1;
    const int block_row = blockIdx.y * 128, block_col = blockIdx.x * BN;
    gemm_core<4, 3>(x + (size_t)t * IN_DIM, T_SEQ * IN_DIM, Wg, 2 * HIDDEN, IN_DIM,
                    block_row, block_col, acc);
#pragma unroll
    for (int mi = 0; mi < 4; mi++)
#pragma unroll
        for (int ni = 0; ni < 4; ni++) {
            int row = block_row + wm * 64 + mi * 16 + (lane >> 2);
            int col = block_col + wn * 32 + ni * 8 + ((lane & 3) << 1);
            float b0 = bg[col], b1 = bg[col + 1];
            *(float2*)&d_Gx[((size_t)row * T_SEQ + t) * (2 * HIDDEN) + col] =
                make_float2(acc[mi][ni][0] + b0, acc[mi][ni][1] + b1);
            *(float2*)&d_Gx[((size_t)(row + 8) * T_SEQ + t) * (2 * HIDDEN) + col] =
                make_float2(acc[mi][ni][2] + b0, acc[mi][ni][3] + b1);
        }
}

// Cx[:, t, :] = x[:, t, :] @ Wc[0:512, :] + bc
__global__ __launch_bounds__(256, 2) void pre_cand_t_kernel(
    const float* __restrict__ x, const float* __restrict__ Wc,
    const float* __restrict__ bc, int t)
{
    float acc[4][4][4];
    const int lane = threadIdx.x & 31, warp = threadIdx.x >> 5;
    const int wm = warp & 1, wn = warp >> 1;
    const int block_row = blockIdx.y * 128, block_col = blockIdx.x * BN;
    gemm_core<4, 3>(x + (size_t)t * IN_DIM, T_SEQ * IN_DIM, Wc, HIDDEN, IN_DIM,
                    block_row, block_col, acc);
#pragma unroll
    for (int mi = 0; mi < 4; mi++)
#pragma unroll
        for (int ni = 0; ni < 4; ni++) {
            int row = block_row + wm * 64 + mi * 16 + (lane >> 2);
            int col = block_col + wn * 32 + ni * 8 + ((lane & 3) << 1);
            float b0 = bc[col], b1 = bc[col + 1];
            *(float2*)&d_Cx[((size_t)row * T_SEQ + t) * HIDDEN + col] =
                make_float2(acc[mi][ni][0] + b0, acc[mi][ni][1] + b1);
            *(float2*)&d_Cx[((size_t)(row + 8) * T_SEQ + t) * HIDDEN + col] =
                make_float2(acc[mi][ni][2] + b0, acc[mi][ni][3] + b1);
        }
}

// ---------------- gate step (MI=2, NS=2, BM=64): grid (16,32) = 512 blocks ----------------
__global__ __launch_bounds__(256) void gate_step_kernel(const float* __restrict__ Wg, int t)
{
    float acc[2][4][4];
    const int lane = threadIdx.x & 31, warp = threadIdx.x >> 5;
    const int wm = warp & 1, wn = warp >> 1;
    const int block_row = blockIdx.y * 64, block_col = blockIdx.x * BN;
    gemm_core<2, 2>(d_H, HIDDEN, Wg + (size_t)IN_DIM * 2 * HIDDEN, 2 * HIDDEN, HIDDEN,
                    block_row, block_col, acc);
    const bool is_reset = (block_col < HIDDEN);   // uniform per block
#pragma unroll
    for (int mi = 0; mi < 2; mi++)
#pragma unroll
        for (int ni = 0; ni < 4; ni++) {
            int row0 = block_row + wm * 32 + mi * 16 + (lane >> 2);
            int col  = block_col + wn * 32 + ni * 8 + ((lane & 3) << 1);
#pragma unroll
            for (int p = 0; p < 2; p++) {
                int row = row0 + p * 8;
                float2 gx = *(const float2*)&d_Gx[((size_t)row * T_SEQ + t) * (2 * HIDDEN) + col];
                float g0 = sigmoidf_(acc[mi][ni][2 * p + 0] + gx.x);
                float g1 = sigmoidf_(acc[mi][ni][2 * p + 1] + gx.y);
                if (is_reset) {
                    size_t hi = (size_t)row * HIDDEN + col;
                    float2 h = *(const float2*)&d_H[hi];
                    *(float2*)&d_RH[hi] = make_float2(g0 * h.x, g1 * h.y);
                } else {
                    size_t ui = (size_t)row * HIDDEN + (col - HIDDEN);
                    *(float2*)&d_U[ui] = make_float2(g0, g1);
                }
            }
        }
}

// ---------------- cand step (MI=2, NS=2, BM=64): grid (8,32) = 256 blocks ----------------
__global__ __launch_bounds__(256) void cand_step_kernel(
    const float* __restrict__ Wc, float* __restrict__ y, int t)
{
    float acc[2][4][4];
    const int lane = threadIdx.x & 31, warp = threadIdx.x >> 5;
    const int wm = warp & 1, wn = warp >> 1;
    const int block_row = blockIdx.y * 64, block_col = blockIdx.x * BN;
    gemm_core<2, 2>(d_RH, HIDDEN, Wc + (size_t)IN_DIM * HIDDEN, HIDDEN, HIDDEN,
                    block_row, block_col, acc);
#pragma unroll
    for (int mi = 0; mi < 2; mi++)
#pragma unroll
        for (int ni = 0; ni < 4; ni++) {
            int row0 = block_row + wm * 32 + mi * 16 + (lane >> 2);
            int col  = block_col + wn * 32 + ni * 8 + ((lane & 3) << 1);
#pragma unroll
            for (int p = 0; p < 2; p++) {
                int row = row0 + p * 8;
                size_t hi = (size_t)row * HIDDEN + col;
                float2 cx = *(const float2*)&d_Cx[((size_t)row * T_SEQ + t) * HIDDEN + col];
                float c0 = tanhf(acc[mi][ni][2 * p + 0] + cx.x);
                float c1 = tanhf(acc[mi][ni][2 * p + 1] + cx.y);
                float2 u = *(const float2*)&d_U[hi];
                float2 h = *(const float2*)&d_H[hi];
                float hn0 = u.x * h.x + (1.0f - u.x) * c0;
                float hn1 = u.y * h.y + (1.0f - u.y) * c1;
                *(float2*)&d_H[hi] = make_float2(hn0, hn1);
                *(float2*)&y[(size_t)row * T_SEQ * HIDDEN + (size_t)t * HIDDEN + col] =
                    make_float2(hn0, hn1);
            }
        }
}

// ---------------- launch ----------------
extern "C" void kernel_launch(void* const* d_in, const int* in_sizes, int n_in,
                              void* d_out, int out_size)
{
    const float* x  = (const float*)d_in[0];  // [B, T, D]
    const float* h0 = (const float*)d_in[1];  // [B, H]
    const float* Wg = (const float*)d_in[2];  // [D+H, 2H]
    const float* bg = (const float*)d_in[3];  // [2H]
    const float* Wc = (const float*)d_in[4];  // [D+H, H]
    const float* bc = (const float*)d_in[5];  // [H]
    float* y = (float*)d_out;                 // [B, T, H]

    const int S_PRE  = SMEM_BYTES(4, 3);   // 107520
    const int S_STEP = SMEM_BYTES(2, 2);   // 53248

    cudaFuncSetAttribute(pre_gate_t_kernel, cudaFuncAttributeMaxDynamicSharedMemorySize, S_PRE);
    cudaFuncSetAttribute(pre_cand_t_kernel, cudaFuncAttributeMaxDynamicSharedMemorySize, S_PRE);
    cudaFuncSetAttribute(gate_step_kernel,  cudaFuncAttributeMaxDynamicSharedMemorySize, S_STEP);
    cudaFuncSetAttribute(cand_step_kernel,  cudaFuncAttributeMaxDynamicSharedMemorySize, S_STEP);

    // Side stream + events: fork precompute off the capture stream, join per step.
    cudaStream_t side;
    cudaStreamCreate(&side);
    cudaEvent_t fork, ev[T_SEQ];
    cudaEventCreateWithFlags(&fork, cudaEventDisableTiming);
    for (int t = 0; t < T_SEQ; t++)
        cudaEventCreateWithFlags(&ev[t], cudaEventDisableTiming);

    // Fork: side stream joins capture via this event.
    cudaEventRecord(fork, 0);
    cudaStreamWaitEvent(side, fork, 0);

    // Side stream: per-timestep x-precompute chunks, event after each t.
    for (int t = 0; t < T_SEQ; t++) {
        pre_gate_t_kernel<<<dim3(2 * HIDDEN / BN, BATCH / 128), 256, S_PRE, side>>>(x, Wg, bg, t);
        pre_cand_t_kernel<<<dim3(HIDDEN / BN, BATCH / 128), 256, S_PRE, side>>>(x, Wc, bc, t);
        cudaEventRecord(ev[t], side);
    }

    // Main stream: init h, then the serial recurrence; step t waits chunk t.
    init_h_kernel<<<(BATCH * HIDDEN / 4) / 256, 256>>>(h0);
    for (int t = 0; t < T_SEQ; t++) {
        cudaStreamWaitEvent(0, ev[t], 0);
        gate_step_kernel<<<dim3(2 * HIDDEN / BN, BATCH / 64), 256, S_STEP>>>(Wg, t);   // (16,32)
        cand_step_kernel<<<dim3(HIDDEN / BN, BATCH / 64), 256, S_STEP>>>(Wc, y, t);    // (8,32)
    }
}

// round 17
// speedup vs baseline: 1.9311x; 1.5243x over previous
#include <cuda_runtime.h>
#include <cuda_fp16.h>
#include <cstdint>
#include <cstddef>

#define T_SEQ   12
#define BATCH   2048
#define IN_DIM  512
#define HIDDEN  1024
#define KTOT    (IN_DIM + HIDDEN)     // 1536

// ---------------- scratch (no runtime allocation allowed) ----------------
__device__ float  d_H  [BATCH * HIDDEN];                       // fp32 hidden state
__device__ float  d_U  [BATCH * HIDDEN];                       // fp32 update gate
__device__ __half d_Hh [BATCH * HIDDEN];                       // fp16 shadow of H (A operand)
__device__ __half d_RHh[BATCH * HIDDEN];                       // fp16 r*h (A operand)
__device__ float  d_Gx[(size_t)BATCH * T_SEQ * 2 * HIDDEN];    // x@Wg_x + bg (fp32)
__device__ float  d_Cx[(size_t)BATCH * T_SEQ * HIDDEN];        // x@Wc_x + bc (fp32)
__device__ __half d_WgTh[(size_t)2 * HIDDEN * KTOT];           // Wg^T [2048][1536] fp16
__device__ __half d_WcTh[(size_t)HIDDEN * KTOT];               // Wc^T [1024][1536] fp16
__device__ __half d_xh [(size_t)BATCH * T_SEQ * IN_DIM];       // x fp16 (A operand)

// ---------------- asm helpers ----------------
__device__ __forceinline__ void cp_async16(uint32_t dst, const void* src) {
    asm volatile("cp.async.cg.shared.global [%0], [%1], 16;\n" :: "r"(dst), "l"(src));
}
__device__ __forceinline__ void mma_f16(float c[4], const uint32_t a[4], const uint32_t b[2]) {
    asm volatile(
        "mma.sync.aligned.m16n8k16.row.col.f32.f16.f16.f32 "
        "{%0,%1,%2,%3}, {%4,%5,%6,%7}, {%8,%9}, {%0,%1,%2,%3};\n"
        : "+f"(c[0]), "+f"(c[1]), "+f"(c[2]), "+f"(c[3])
        : "r"(a[0]), "r"(a[1]), "r"(a[2]), "r"(a[3]), "r"(b[0]), "r"(b[1]));
}
__device__ __forceinline__ float sigmoidf_(float x) { return 1.0f / (1.0f + expf(-x)); }

// ---------------- fp16 GEMM core: BM=32*MI, BN=128, BK=64 halves, 256 threads ----------------
// Smem tiles stored as uint32 WORDS; one word = 2 k-consecutive halves (half2).
// A tile:  BM rows  x 32 words, row stride 36 words (same bank math as proven tf32 core).
// BT tile: BN n-rows x 32 words, row stride 36 words (weights pre-transposed, K-major).
// C[row][n] = sum_k A[row][k] * BT[n][k]. Scalar LDS fragments only — no ldmatrix.
#define BN 128
#define BK 64                 // halves per slab = 32 words
#define SW 36                 // row stride in words (144 B)
#define SA_WORDS_MI(MI)    (32 * (MI) * SW)
#define SB_WORDS           (BN * SW)
#define STAGE_WORDS_MI(MI) (SA_WORDS_MI(MI) + SB_WORDS)
#define SMEM_BYTES(MI, NS) ((NS) * STAGE_WORDS_MI(MI) * 4)
// MI=2,NS=2: 55296   MI=4,NS=3: 110592

template<int MI>
__device__ __forceinline__ void load_stage_h(
    uint32_t stage,                        // byte address in smem
    const __half* __restrict__ A, int lda, // halves
    const __half* __restrict__ BT, int ldb,
    int block_row, int block_col, int k0, int tid)
{
#pragma unroll
    for (int i = 0; i < MI; i++) {                 // A: 32*MI rows x 8 chunks(16B = 8 halves)
        int idx = tid + i * 256;
        int r = idx >> 3, c8 = (idx & 7);
        cp_async16(stage + (uint32_t)(r * SW * 4 + c8 * 16),
                   A + (size_t)(block_row + r) * lda + k0 + c8 * 8);
    }
#pragma unroll
    for (int i = 0; i < 4; i++) {                  // BT: 128 n-rows x 8 chunks(16B)
        int idx = tid + i * 256;
        int r = idx >> 3, c8 = (idx & 7);
        cp_async16(stage + (uint32_t)(SA_WORDS_MI(MI) * 4 + r * SW * 4 + c8 * 16),
                   BT + (size_t)(block_col + r) * ldb + k0 + c8 * 8);
    }
    asm volatile("cp.async.commit_group;\n" ::: "memory");
}

template<int MI>
__device__ __forceinline__ void compute_slab_h(
    const uint32_t* __restrict__ cA, const uint32_t* __restrict__ cB,
    int lane, int wm, int wn, float (&acc)[MI][4][4])
{
#pragma unroll
    for (int ks = 0; ks < 4; ks++) {               // 4 x k16; kk = word offset
        const int kk = ks * 8;
        uint32_t af[MI][4], bf[4][2];
#pragma unroll
        for (int mi = 0; mi < MI; mi++) {
            int rb = wm * (MI * 16) + mi * 16 + (lane >> 2);
            const uint32_t* p = cA + rb * SW + kk + (lane & 3);
            af[mi][0] = p[0];              // (row,   k lo-pair)
            af[mi][1] = p[8 * SW];         // (row+8, k lo-pair)
            af[mi][2] = p[4];              // (row,   k hi-pair)
            af[mi][3] = p[8 * SW + 4];     // (row+8, k hi-pair)
        }
#pragma unroll
        for (int ni = 0; ni < 4; ni++) {
            int nb = wn * 32 + ni * 8 + (lane >> 2);
            const uint32_t* q = cB + nb * SW + kk + (lane & 3);
            bf[ni][0] = q[0];
            bf[ni][1] = q[4];
        }
#pragma unroll
        for (int mi = 0; mi < MI; mi++)
#pragma unroll
            for (int ni = 0; ni < 4; ni++)
                mma_f16(acc[mi][ni], af[mi], bf[ni]);
    }
}

template<int MI, int NS>
__device__ __forceinline__ void gemm_core_h(
    const __half* __restrict__ A, int lda,
    const __half* __restrict__ BT, int ldb,
    int K, int block_row, int block_col,
    float (&acc)[MI][4][4])
{
    extern __shared__ uint32_t smem[];
    const int tid  = threadIdx.x;
    const int lane = tid & 31;
    const int warp = tid >> 5;
    const int wm   = warp & 1;
    const int wn   = warp >> 1;
    const uint32_t sbase = (uint32_t)__cvta_generic_to_shared(smem);

#pragma unroll
    for (int mi = 0; mi < MI; mi++)
#pragma unroll
        for (int ni = 0; ni < 4; ni++)
#pragma unroll
            for (int r = 0; r < 4; r++) acc[mi][ni][r] = 0.0f;

    const int nsteps = K / BK;

    if (NS == 3) {
        load_stage_h<MI>(sbase, A, lda, BT, ldb, block_row, block_col, 0, tid);
        load_stage_h<MI>(sbase + STAGE_WORDS_MI(MI) * 4, A, lda, BT, ldb,
                         block_row, block_col, BK, tid);
        int mbuf = 0, lbuf = 2;
        for (int s = 0; s < nsteps; s++) {
            if (s == nsteps - 1) asm volatile("cp.async.wait_group 0;\n" ::: "memory");
            else                 asm volatile("cp.async.wait_group 1;\n" ::: "memory");
            __syncthreads();
            if (s + 2 < nsteps)
                load_stage_h<MI>(sbase + (uint32_t)lbuf * STAGE_WORDS_MI(MI) * 4,
                                 A, lda, BT, ldb, block_row, block_col, (s + 2) * BK, tid);
            lbuf = (lbuf == 2) ? 0 : lbuf + 1;
            const uint32_t* cA = smem + (size_t)mbuf * STAGE_WORDS_MI(MI);
            mbuf = (mbuf == 2) ? 0 : mbuf + 1;
            compute_slab_h<MI>(cA, cA + SA_WORDS_MI(MI), lane, wm, wn, acc);
        }
    } else {
        load_stage_h<MI>(sbase, A, lda, BT, ldb, block_row, block_col, 0, tid);
        for (int s = 0; s < nsteps; s++) {
            const int cur = s & 1;
            if (s + 1 < nsteps) {
                load_stage_h<MI>(sbase + (uint32_t)((s + 1) & 1) * STAGE_WORDS_MI(MI) * 4,
                                 A, lda, BT, ldb, block_row, block_col, (s + 1) * BK, tid);
                asm volatile("cp.async.wait_group 1;\n" ::: "memory");
            } else {
                asm volatile("cp.async.wait_group 0;\n" ::: "memory");
            }
            __syncthreads();
            const uint32_t* cA = smem + (size_t)cur * STAGE_WORDS_MI(MI);
            compute_slab_h<MI>(cA, cA + SA_WORDS_MI(MI), lane, wm, wn, acc);
            __syncthreads();
        }
    }
}

// ---------------- conversion / init kernels ----------------
// IMPORTANT: all __device__ arrays are referenced INSIDE kernels only — never
// passed as kernel arguments from host (host sees the shadow symbol, and with
// GB300 ATS the writes silently land in host memory).
__global__ __launch_bounds__(256) void xh_convert_kernel(const float* __restrict__ src) {
    size_t i = (size_t)blockIdx.x * 256 + threadIdx.x;
    float4 v = ((const float4*)src)[i];
    ((__half2*)d_xh)[2 * i]     = __floats2half2_rn(v.x, v.y);
    ((__half2*)d_xh)[2 * i + 1] = __floats2half2_rn(v.z, v.w);
}
__global__ __launch_bounds__(256) void init_h_kernel(const float* __restrict__ src) {
    size_t i = (size_t)blockIdx.x * 256 + threadIdx.x;
    float4 v = ((const float4*)src)[i];
    ((float4*)d_H)[i] = v;
    ((__half2*)d_Hh)[2 * i]     = __floats2half2_rn(v.x, v.y);
    ((__half2*)d_Hh)[2 * i + 1] = __floats2half2_rn(v.z, v.w);
}
// d_WgTh[c][r] = (half) Wg[r][c];  Wg: [KTOT][2H] fp32.  grid (2H/32, KTOT/32)
__global__ __launch_bounds__(256) void wgT_convert_kernel(const float* __restrict__ Wg) {
    __shared__ float tile[32][33];
    const int cb = blockIdx.x * 32, rb = blockIdx.y * 32;
    const int tx = threadIdx.x & 31, ty = threadIdx.x >> 5;   // ty 0..7
#pragma unroll
    for (int j = 0; j < 4; j++)
        tile[ty + j * 8][tx] = Wg[(size_t)(rb + ty + j * 8) * (2 * HIDDEN) + cb + tx];
    __syncthreads();
#pragma unroll
    for (int j = 0; j < 4; j++)
        d_WgTh[(size_t)(cb + ty + j * 8) * KTOT + rb + tx] =
            __float2half_rn(tile[tx][ty + j * 8]);
}
// d_WcTh[c][r] = (half) Wc[r][c];  Wc: [KTOT][H] fp32.  grid (H/32, KTOT/32)
__global__ __launch_bounds__(256) void wcT_convert_kernel(const float* __restrict__ Wc) {
    __shared__ float tile[32][33];
    const int cb = blockIdx.x * 32, rb = blockIdx.y * 32;
    const int tx = threadIdx.x & 31, ty = threadIdx.x >> 5;
#pragma unroll
    for (int j = 0; j < 4; j++)
        tile[ty + j * 8][tx] = Wc[(size_t)(rb + ty + j * 8) * HIDDEN + cb + tx];
    __syncthreads();
#pragma unroll
    for (int j = 0; j < 4; j++)
        d_WcTh[(size_t)(cb + ty + j * 8) * KTOT + rb + tx] =
            __float2half_rn(tile[tx][ty + j * 8]);
}

// ---------------- precompute kernels (MI=4, NS=3, BM=128, rows = B*T) ----------------
__global__ __launch_bounds__(256, 2) void pre_gate_kernel(const float* __restrict__ bg)
{
    float acc[4][4][4];
    const int lane = threadIdx.x & 31, warp = threadIdx.x >> 5;
    const int wm = warp & 1, wn = warp >> 1;
    const int block_row = blockIdx.y * 128, block_col = blockIdx.x * BN;
    gemm_core_h<4, 3>(d_xh, IN_DIM, d_WgTh, KTOT, IN_DIM, block_row, block_col, acc);
#pragma unroll
    for (int mi = 0; mi < 4; mi++)
#pragma unroll
        for (int ni = 0; ni < 4; ni++) {
            int row = block_row + wm * 64 + mi * 16 + (lane >> 2);
            int col = block_col + wn * 32 + ni * 8 + ((lane & 3) << 1);
            float b0 = bg[col], b1 = bg[col + 1];
            *(float2*)&d_Gx[(size_t)row * (2 * HIDDEN) + col] =
                make_float2(acc[mi][ni][0] + b0, acc[mi][ni][1] + b1);
            *(float2*)&d_Gx[(size_t)(row + 8) * (2 * HIDDEN) + col] =
                make_float2(acc[mi][ni][2] + b0, acc[mi][ni][3] + b1);
        }
}
__global__ __launch_bounds__(256, 2) void pre_cand_kernel(const float* __restrict__ bc)
{
    float acc[4][4][4];
    const int lane = threadIdx.x & 31, warp = threadIdx.x >> 5;
    const int wm = warp & 1, wn = warp >> 1;
    const int block_row = blockIdx.y * 128, block_col = blockIdx.x * BN;
    gemm_core_h<4, 3>(d_xh, IN_DIM, d_WcTh, KTOT, IN_DIM, block_row, block_col, acc);
#pragma unroll
    for (int mi = 0; mi < 4; mi++)
#pragma unroll
        for (int ni = 0; ni < 4; ni++) {
            int row = block_row + wm * 64 + mi * 16 + (lane >> 2);
            int col = block_col + wn * 32 + ni * 8 + ((lane & 3) << 1);
            float b0 = bc[col], b1 = bc[col + 1];
            *(float2*)&d_Cx[(size_t)row * HIDDEN + col] =
                make_float2(acc[mi][ni][0] + b0, acc[mi][ni][1] + b1);
            *(float2*)&d_Cx[(size_t)(row + 8) * HIDDEN + col] =
                make_float2(acc[mi][ni][2] + b0, acc[mi][ni][3] + b1);
        }
}

// ---------------- gate step (MI=2, NS=2, BM=64): grid (16,32) ----------------
__global__ __launch_bounds__(256) void gate_step_kernel(int t)
{
    float acc[2][4][4];
    const int lane = threadIdx.x & 31, warp = threadIdx.x >> 5;
    const int wm = warp & 1, wn = warp >> 1;
    const int block_row = blockIdx.y * 64, block_col = blockIdx.x * BN;
    gemm_core_h<2, 2>(d_Hh, HIDDEN, d_WgTh + IN_DIM, KTOT, HIDDEN,
                      block_row, block_col, acc);
    const bool is_reset = (block_col < HIDDEN);   // uniform per block
#pragma unroll
    for (int mi = 0; mi < 2; mi++)
#pragma unroll
        for (int ni = 0; ni < 4; ni++) {
            int row0 = block_row + wm * 32 + mi * 16 + (lane >> 2);
            int col  = block_col + wn * 32 + ni * 8 + ((lane & 3) << 1);
#pragma unroll
            for (int p = 0; p < 2; p++) {
                int row = row0 + p * 8;
                float2 gx = *(const float2*)&d_Gx[((size_t)row * T_SEQ + t) * (2 * HIDDEN) + col];
                float g0 = sigmoidf_(acc[mi][ni][2 * p + 0] + gx.x);
                float g1 = sigmoidf_(acc[mi][ni][2 * p + 1] + gx.y);
                if (is_reset) {
                    size_t hi = (size_t)row * HIDDEN + col;
                    float2 h = *(const float2*)&d_H[hi];
                    *(__half2*)&d_RHh[hi] = __floats2half2_rn(g0 * h.x, g1 * h.y);
                } else {
                    size_t ui = (size_t)row * HIDDEN + (col - HIDDEN);
                    *(float2*)&d_U[ui] = make_float2(g0, g1);
                }
            }
        }
}

// ---------------- cand step (MI=2, NS=2, BM=64): grid (8,32) ----------------
__global__ __launch_bounds__(256) void cand_step_kernel(float* __restrict__ y, int t)
{
    float acc[2][4][4];
    const int lane = threadIdx.x & 31, warp = threadIdx.x >> 5;
    const int wm = warp & 1, wn = warp >> 1;
    const int block_row = blockIdx.y * 64, block_col = blockIdx.x * BN;
    gemm_core_h<2, 2>(d_RHh, HIDDEN, d_WcTh + IN_DIM, KTOT, HIDDEN,
                      block_row, block_col, acc);
#pragma unroll
    for (int mi = 0; mi < 2; mi++)
#pragma unroll
        for (int ni = 0; ni < 4; ni++) {
            int row0 = block_row + wm * 32 + mi * 16 + (lane >> 2);
            int col  = block_col + wn * 32 + ni * 8 + ((lane & 3) << 1);
#pragma unroll
            for (int p = 0; p < 2; p++) {
                int row = row0 + p * 8;
                size_t hi = (size_t)row * HIDDEN + col;
                float2 cx = *(const float2*)&d_Cx[((size_t)row * T_SEQ + t) * HIDDEN + col];
                float c0 = tanhf(acc[mi][ni][2 * p + 0] + cx.x);
                float c1 = tanhf(acc[mi][ni][2 * p + 1] + cx.y);
                float2 u = *(const float2*)&d_U[hi];
                float2 h = *(const float2*)&d_H[hi];
                float hn0 = u.x * h.x + (1.0f - u.x) * c0;
                float hn1 = u.y * h.y + (1.0f - u.y) * c1;
                *(float2*)&d_H[hi]   = make_float2(hn0, hn1);
                *(__half2*)&d_Hh[hi] = __floats2half2_rn(hn0, hn1);
                *(float2*)&y[(size_t)row * T_SEQ * HIDDEN + (size_t)t * HIDDEN + col] =
                    make_float2(hn0, hn1);
            }
        }
}

// ---------------- launch ----------------
extern "C" void kernel_launch(void* const* d_in, const int* in_sizes, int n_in,
                              void* d_out, int out_size)
{
    const float* x  = (const float*)d_in[0];  // [B, T, D]
    const float* h0 = (const float*)d_in[1];  // [B, H]
    const float* Wg = (const float*)d_in[2];  // [D+H, 2H]
    const float* bg = (const float*)d_in[3];  // [2H]
    const float* Wc = (const float*)d_in[4];  // [D+H, H]
    const float* bc = (const float*)d_in[5];  // [H]
    float* y = (float*)d_out;                 // [B, T, H]

    const int S_PRE  = SMEM_BYTES(4, 3);   // 110592
    const int S_STEP = SMEM_BYTES(2, 2);   // 55296

    cudaFuncSetAttribute(pre_gate_kernel,  cudaFuncAttributeMaxDynamicSharedMemorySize, S_PRE);
    cudaFuncSetAttribute(pre_cand_kernel,  cudaFuncAttributeMaxDynamicSharedMemorySize, S_PRE);
    cudaFuncSetAttribute(gate_step_kernel, cudaFuncAttributeMaxDynamicSharedMemorySize, S_STEP);
    cudaFuncSetAttribute(cand_step_kernel, cudaFuncAttributeMaxDynamicSharedMemorySize, S_STEP);

    // conversions (device arrays written inside the kernels — no symbols as args)
    wgT_convert_kernel<<<dim3(2 * HIDDEN / 32, KTOT / 32), 256>>>(Wg);
    wcT_convert_kernel<<<dim3(HIDDEN / 32, KTOT / 32), 256>>>(Wc);
    { size_t n = (size_t)BATCH * T_SEQ * IN_DIM;
      xh_convert_kernel<<<(int)(n / 4 / 256), 256>>>(x); }
    init_h_kernel<<<(BATCH * HIDDEN / 4) / 256, 256>>>(h0);

    // Precompute x-dependent halves (rows = B*T)
    pre_gate_kernel<<<dim3(2 * HIDDEN / BN, (BATCH * T_SEQ) / 128), 256, S_PRE>>>(bg);
    pre_cand_kernel<<<dim3(HIDDEN / BN, (BATCH * T_SEQ) / 128), 256, S_PRE>>>(bc);

    // Serial recurrence
    for (int t = 0; t < T_SEQ; t++) {
        gate_step_kernel<<<dim3(2 * HIDDEN / BN, BATCH / 64), 256, S_STEP>>>(t);      // (16,32)
        cand_step_kernel<<<dim3(HIDDEN / BN, BATCH / 64), 256, S_STEP>>>(y, t);       // (8,32)
    }
}